// round 11
// baseline (speedup 1.0000x reference)
#include <cuda_runtime.h>
#include <cuda_fp16.h>
#include <math.h>
#include <stdint.h>

#define BATCH   128
#define HIDDEN  1024
#define EMBED   512
#define VOCAB   32000
#define VOCAB_PAD 32032       // 286*112; padded weight rows are zero-initialized
#define MAXLEN  48
#define GATES4  4096
#define KL      1024          // logits K
#define KG      1536          // gates K
#define LTILE   112           // logits N tile
#define NT2     286           // logits tiles (285 full + 1 ragged)
#define KSPLIT  4             // gates split-K (K=384 each)

// gates kernel (R7 config): K-chunk 64, SW128, 2 stages
#define G_STAGE 49152
#define G_SMEM  (2*G_STAGE)
// logits kernel: K-chunk 32, SW64, 3 stages; stage = A 2x8KB + B 2x7KB = 30720
#define L_STAGE 30720
#define L_SMEM  (3*L_STAGE + 1024)   // +1KB guard for wn1 predicated-off overread safety

// ---------------- persistent device state (no allocation) --------------------
__device__ __align__(16) __half g_a0[BATCH*KG];   // A: cols [0,512)=x, [512,1536)=h
__device__ __align__(16) __half g_a1[BATCH*KG];
__device__ __align__(16) __half g_w0[(size_t)VOCAB_PAD*KL];   // zero-init padding rows
__device__ __align__(16) __half g_w1[(size_t)VOCAB_PAD*KL];
__device__ __align__(16) __half g_g0[(size_t)GATES4*KG];
__device__ __align__(16) __half g_g1[(size_t)GATES4*KG];
__device__ float g_c[BATCH*HIDDEN];
__device__ float g_part[KSPLIT*BATCH*GATES4];
__device__ float g_pval[NT2*BATCH];
__device__ int   g_pidx[NT2*BATCH];

// ---------------- ptx helpers (base-family PTX, sm_80+) ----------------------
__device__ __forceinline__ uint32_t smem_u32(const void* p) {
    uint32_t a;
    asm("{ .reg .u64 t; cvta.to.shared.u64 t, %1; cvt.u32.u64 %0, t; }" : "=r"(a) : "l"(p));
    return a;
}
__device__ __forceinline__ void cpa16(uint32_t dst, const void* src) {
    asm volatile("cp.async.cg.shared.global [%0], [%1], 16;" :: "r"(dst), "l"(src));
}
__device__ __forceinline__ void cpa_commit() {
    asm volatile("cp.async.commit_group;" ::: "memory");
}
template<int N> __device__ __forceinline__ void cpa_wait() {
    asm volatile("cp.async.wait_group %0;" :: "n"(N) : "memory");
}
__device__ __forceinline__ void ldsm4(uint32_t* r, uint32_t addr) {
    asm volatile("ldmatrix.sync.aligned.m8n8.x4.shared.b16 {%0,%1,%2,%3}, [%4];"
                 : "=r"(r[0]), "=r"(r[1]), "=r"(r[2]), "=r"(r[3]) : "r"(addr));
}
__device__ __forceinline__ void mma16816(float* c, const uint32_t* a, uint32_t b0, uint32_t b1) {
    asm volatile(
        "mma.sync.aligned.m16n8k16.row.col.f32.f16.f16.f32 "
        "{%0,%1,%2,%3}, {%4,%5,%6,%7}, {%8,%9}, {%0,%1,%2,%3};"
        : "+f"(c[0]), "+f"(c[1]), "+f"(c[2]), "+f"(c[3])
        : "r"(a[0]), "r"(a[1]), "r"(a[2]), "r"(a[3]), "r"(b0), "r"(b1));
}
__device__ __forceinline__ uint32_t swz128(uint32_t off) { return off ^ ((off >> 3) & 0x70); }
__device__ __forceinline__ uint32_t swz64(uint32_t off)  { return off ^ ((off >> 3) & 0x30); }

__device__ __forceinline__ void split2(float x, __half& a, __half& b) {
    a = __float2half_rn(x);
    b = __float2half_rn(x - __half2float(a));
}

// ---------------- weight conversion ------------------------------------------
__global__ void conv_wout_kernel(const float* __restrict__ w) {
    size_t i4 = ((size_t)blockIdx.x * 256 + threadIdx.x) * 4;
    if (i4 >= (size_t)VOCAB * KL) return;
    float4 v = *(const float4*)&w[i4];
    __half a[4], b[4];
    split2(v.x, a[0], b[0]); split2(v.y, a[1], b[1]);
    split2(v.z, a[2], b[2]); split2(v.w, a[3], b[3]);
#pragma unroll
    for (int j = 0; j < 4; j++) { g_w0[i4+j] = a[j]; g_w1[i4+j] = b[j]; }
}
__global__ void conv_wg_kernel(const float* __restrict__ w_ih, const float* __restrict__ w_hh) {
    size_t i4 = ((size_t)blockIdx.x * 256 + threadIdx.x) * 4;
    if (i4 >= (size_t)GATES4 * KG) return;
    int n = (int)(i4 / KG), k = (int)(i4 % KG);
    float4 v;
    if (k < EMBED) v = *(const float4*)&w_ih[(size_t)n*EMBED + k];
    else           v = *(const float4*)&w_hh[(size_t)n*HIDDEN + (k - EMBED)];
    __half a[4], b[4];
    split2(v.x, a[0], b[0]); split2(v.y, a[1], b[1]);
    split2(v.z, a[2], b[2]); split2(v.w, a[3], b[3]);
#pragma unroll
    for (int j = 0; j < 4; j++) { g_g0[i4+j] = a[j]; g_g1[i4+j] = b[j]; }
}

// ---------------- init -------------------------------------------------------
__global__ void init_kernel(const float* __restrict__ eh, const float* __restrict__ ec,
                            const float* __restrict__ emb, const int* __restrict__ sos,
                            float* __restrict__ out0)
{
    int idx = blockIdx.x * 256 + threadIdx.x;
    if (idx < BATCH*HIDDEN) {
        int bb = idx >> 10, j = idx & 1023;
        __half a, b;
        split2(eh[idx], a, b);
        g_a0[bb*KG + 512 + j] = a; g_a1[bb*KG + 512 + j] = b;
        g_c[idx] = ec[idx];
    }
    if (idx < BATCH*EMBED) {
        int bb = idx >> 9, j = idx & 511;
        __half a, b;
        split2(emb[(size_t)sos[0]*EMBED + j], a, b);
        g_a0[bb*KG + j] = a; g_a1[bb*KG + j] = b;
    }
    if (idx < BATCH*VOCAB) out0[idx] = 0.0f;
}

// ---------------- gates GEMM (unchanged R7 config) ---------------------------
// C[128 x 64-tile] = A0*B0 + A0*B1 + A1*B0, K-chunk 64, SW128, 2-stage.
__global__ __launch_bounds__(256, 2) void gates_gemm()
{
    extern __shared__ char smem[];
    const uint32_t sbase = smem_u32(smem);
    const int tid  = threadIdx.x;
    const int lane = tid & 31;
    const int warp = tid >> 5;
    const int wm = warp >> 1, wn = warp & 1;
    const int m_base = wm * 32, n_base = wn * 32;
    const int n0     = blockIdx.x * 64;
    const int kStart = blockIdx.y * (KG / KSPLIT);
    const int NC = (KG / KSPLIT) / 64;   // 6

    auto load_stage = [&](int buf, int c) {
        uint32_t sdst = sbase + buf * G_STAGE;
        const int kc = kStart + c * 64;
#pragma unroll
        for (int i = 0; i < 12; i++) {
            const int idx = i * 256 + tid;
            if (idx < 2048) {
                const int t = idx >> 10, rem = idx & 1023;
                const int row = rem >> 3, ch = rem & 7;
                cpa16(sdst + t * 16384 + swz128((uint32_t)(row * 128 + ch * 16)),
                      (t ? g_a1 : g_a0) + row * KG + kc + ch * 8);
            } else {
                const int t = (idx - 2048) >> 9, rem = idx & 511;
                const int row = rem >> 3, ch = rem & 7;
                cpa16(sdst + 32768 + t * 8192 + swz128((uint32_t)(row * 128 + ch * 16)),
                      (t ? g_g1 : g_g0) + (size_t)(n0 + row) * KG + kc + ch * 8);
            }
        }
    };

    float acc[2][4][4];
#pragma unroll
    for (int i = 0; i < 2; i++)
#pragma unroll
        for (int j = 0; j < 4; j++)
#pragma unroll
            for (int q = 0; q < 4; q++) acc[i][j][q] = 0.f;

    load_stage(0, 0); cpa_commit();

#pragma unroll 1
    for (int c = 0; c < NC; c++) {
        if (c + 1 < NC) { load_stage((c + 1) & 1, c + 1); cpa_commit(); cpa_wait<1>(); }
        else            { cpa_wait<0>(); }
        __syncthreads();

        const uint32_t sb  = sbase + (c & 1) * G_STAGE;
        const uint32_t sA0 = sb, sA1 = sb + 16384, sB0 = sb + 32768, sB1 = sb + 40960;
#pragma unroll
        for (int ks = 0; ks < 4; ks++) {
            const uint32_t kb = (uint32_t)(ks * 32 + ((lane >> 4) << 4));
            uint32_t a0[2][4], a1[2][4], b0[2][4], b1[2][4];
#pragma unroll
            for (int mt = 0; mt < 2; mt++) {
                const uint32_t roff = swz128((uint32_t)((m_base + mt*16 + (lane & 15)) * 128) + kb);
                ldsm4(a0[mt], sA0 + roff);
                ldsm4(a1[mt], sA1 + roff);
            }
#pragma unroll
            for (int nh = 0; nh < 2; nh++) {
                const uint32_t roff = swz128((uint32_t)((n_base + nh*16 + (lane & 15)) * 128) + kb);
                ldsm4(b0[nh], sB0 + roff);
                ldsm4(b1[nh], sB1 + roff);
            }
#pragma unroll
            for (int mt = 0; mt < 2; mt++)
#pragma unroll
                for (int nt = 0; nt < 4; nt++) {
                    const int nh = nt >> 1, hi = nt & 1;
                    mma16816(acc[mt][nt], a0[mt], b0[nh][hi], b0[nh][hi + 2]);
                }
#pragma unroll
            for (int mt = 0; mt < 2; mt++)
#pragma unroll
                for (int nt = 0; nt < 4; nt++) {
                    const int nh = nt >> 1, hi = nt & 1;
                    mma16816(acc[mt][nt], a0[mt], b1[nh][hi], b1[nh][hi + 2]);
                }
#pragma unroll
            for (int mt = 0; mt < 2; mt++)
#pragma unroll
                for (int nt = 0; nt < 4; nt++) {
                    const int nh = nt >> 1, hi = nt & 1;
                    mma16816(acc[mt][nt], a1[mt], b0[nh][hi], b0[nh][hi + 2]);
                }
        }
        __syncthreads();
    }

    float* o = g_part + (size_t)blockIdx.y * BATCH * GATES4;
#pragma unroll
    for (int mt = 0; mt < 2; mt++) {
        const int r0 = m_base + mt * 16 + (lane >> 2);
#pragma unroll
        for (int nt = 0; nt < 4; nt++) {
            const int col = n0 + n_base + nt * 8 + (lane & 3) * 2;
            *(float2*)&o[(size_t)r0 * GATES4 + col]       = make_float2(acc[mt][nt][0], acc[mt][nt][1]);
            *(float2*)&o[(size_t)(r0 + 8) * GATES4 + col] = make_float2(acc[mt][nt][2], acc[mt][nt][3]);
        }
    }
}

// ---------------- logits GEMM: N-tile 112, K-chunk 32, SW64, 3-stage ---------
// warp map: wm = warp&3 (SMSP id), wn = warp>>2. wn0: cols [0,64), wn1: [64,112).
__global__ __launch_bounds__(256, 2) void logits_gemm(
    const float* __restrict__ bias, float* __restrict__ out)
{
    extern __shared__ char smem[];
    const uint32_t sbase = smem_u32(smem);
    const int tid  = threadIdx.x;
    const int lane = tid & 31;
    const int warp = tid >> 5;
    const int wm = warp & 3, wn = warp >> 2;
    const int m_base = wm * 32;
    const int nwoff  = wn * 64;
    const int NH = wn ? 3 : 4;       // 16-col ldsm groups per warp
    const int n0 = blockIdx.x * LTILE;
    const int NC = KL / 32;          // 32 chunks

    auto load_stage = [&](int buf, int c) {
        uint32_t sdst = sbase + buf * L_STAGE;
        const int kc = c * 32;
#pragma unroll
        for (int i = 0; i < 8; i++) {
            const int idx = i * 256 + tid;            // 0..2047, need 1920
            if (idx < 1024) {                          // A: 2 splits x 128 rows x 4 ch
                const int t = idx >> 9, rem = idx & 511;
                const int row = rem >> 2, ch = rem & 3;
                cpa16(sdst + t * 8192 + swz64((uint32_t)(row * 64 + ch * 16)),
                      (t ? g_a1 : g_a0) + row * KG + 512 + kc + ch * 8);
            } else if (idx < 1920) {                   // B: 2 splits x 112 rows x 4 ch
                const int j = idx - 1024;
                const int t = j / 448, rem = j % 448;
                const int row = rem >> 2, ch = rem & 3;
                cpa16(sdst + 16384 + t * 7168 + swz64((uint32_t)(row * 64 + ch * 16)),
                      (t ? g_w1 : g_w0) + (size_t)(n0 + row) * KL + kc + ch * 8);
            }
        }
    };

    float acc[2][8][4];
#pragma unroll
    for (int i = 0; i < 2; i++)
#pragma unroll
        for (int j = 0; j < 8; j++)
#pragma unroll
            for (int q = 0; q < 4; q++) acc[i][j][q] = 0.f;

    load_stage(0, 0); cpa_commit();
    load_stage(1, 1); cpa_commit();

#pragma unroll 1
    for (int c = 0; c < NC; c++) {
        if (c + 2 < NC) { load_stage((c + 2) % 3, c + 2); cpa_commit(); cpa_wait<2>(); }
        else if (c + 1 < NC) { cpa_wait<1>(); }
        else                 { cpa_wait<0>(); }
        __syncthreads();

        const uint32_t sb  = sbase + (c % 3) * L_STAGE;
        const uint32_t sA0 = sb, sA1 = sb + 8192, sB0 = sb + 16384, sB1 = sb + 23552;
#pragma unroll
        for (int ks = 0; ks < 2; ks++) {
            const uint32_t kb = (uint32_t)(ks * 32 + ((lane >> 4) << 4));
            uint32_t a0[2][4], a1[2][4], b[4][4];
#pragma unroll
            for (int mt = 0; mt < 2; mt++) {
                const uint32_t roff = swz64((uint32_t)((m_base + mt*16 + (lane & 15)) * 64) + kb);
                ldsm4(a0[mt], sA0 + roff);
                ldsm4(a1[mt], sA1 + roff);
            }
#pragma unroll
            for (int nh = 0; nh < 4; nh++)
                if (nh < NH)
                    ldsm4(b[nh], sB0 + swz64((uint32_t)((nwoff + nh*16 + (lane & 15)) * 64) + kb));
#pragma unroll
            for (int mt = 0; mt < 2; mt++)
#pragma unroll
                for (int nt = 0; nt < 8; nt++)
                    if (nt < 2*NH)
                        mma16816(acc[mt][nt], a0[mt], b[nt>>1][nt&1], b[nt>>1][(nt&1) + 2]);
#pragma unroll
            for (int mt = 0; mt < 2; mt++)
#pragma unroll
                for (int nt = 0; nt < 8; nt++)
                    if (nt < 2*NH)
                        mma16816(acc[mt][nt], a1[mt], b[nt>>1][nt&1], b[nt>>1][(nt&1) + 2]);
#pragma unroll
            for (int nh = 0; nh < 4; nh++)
                if (nh < NH)
                    ldsm4(b[nh], sB1 + swz64((uint32_t)((nwoff + nh*16 + (lane & 15)) * 64) + kb));
#pragma unroll
            for (int mt = 0; mt < 2; mt++)
#pragma unroll
                for (int nt = 0; nt < 8; nt++)
                    if (nt < 2*NH)
                        mma16816(acc[mt][nt], a0[mt], b[nt>>1][nt&1], b[nt>>1][(nt&1) + 2]);
        }
        __syncthreads();
    }

    // ---- epilogue: bias, masked store, fused partial argmax ----
    float* rv = (float*)smem;
    int*   ri = (int*)(smem + 1024);

#pragma unroll
    for (int mt = 0; mt < 2; mt++) {
#pragma unroll
        for (int half = 0; half < 2; half++) {
            const int row = m_base + mt * 16 + (lane >> 2) + half * 8;
            float best = -INFINITY; int bidx = 0x7fffffff;
#pragma unroll
            for (int nt = 0; nt < 8; nt++) {
                if (nt < 2*NH) {
                    const int col = n0 + nwoff + nt * 8 + (lane & 3) * 2;
                    if (col < VOCAB) {
                        float2 bb = *(const float2*)&bias[col];
                        float v0 = acc[mt][nt][half*2]   + bb.x;
                        float v1 = acc[mt][nt][half*2+1] + bb.y;
                        *(float2*)&out[(size_t)row * VOCAB + col] = make_float2(v0, v1);
                        if (v0 > best) { best = v0; bidx = col; }
                        if (v1 > best) { best = v1; bidx = col + 1; }
                    }
                }
            }
#pragma unroll
            for (int off = 1; off <= 2; off <<= 1) {
                float ov = __shfl_xor_sync(0xffffffffu, best, off);
                int   oi = __shfl_xor_sync(0xffffffffu, bidx, off);
                if (ov > best || (ov == best && oi < bidx)) { best = ov; bidx = oi; }
            }
            if ((lane & 3) == 0) { rv[row * 2 + wn] = best; ri[row * 2 + wn] = bidx; }
        }
    }
    __syncthreads();
    if (tid < 128) {
        float best = rv[tid * 2]; int bidx = ri[tid * 2];
        float ov = rv[tid * 2 + 1]; int oi = ri[tid * 2 + 1];
        if (ov > best || (ov == best && oi < bidx)) { best = ov; bidx = oi; }
        g_pval[blockIdx.x * BATCH + tid] = best;
        g_pidx[blockIdx.x * BATCH + tid] = bidx;
    }
}

// ---------------- LSTM elementwise (sums split-K partials) -------------------
__global__ void lstm_kernel(const float* __restrict__ b_ih, const float* __restrict__ b_hh)
{
    int idx = blockIdx.x * 256 + threadIdx.x;     // < 128*1024
    int b = idx >> 10, j = idx & 1023;
    const int o = b * GATES4 + j;
    float ig = b_ih[j]        + b_hh[j];
    float fg = b_ih[1024 + j] + b_hh[1024 + j];
    float gg = b_ih[2048 + j] + b_hh[2048 + j];
    float og = b_ih[3072 + j] + b_hh[3072 + j];
#pragma unroll
    for (int s = 0; s < KSPLIT; s++) {
        const float* P = g_part + (size_t)s * BATCH * GATES4;
        ig += P[o]; fg += P[o + 1024]; gg += P[o + 2048]; og += P[o + 3072];
    }
    float i_s = 1.f / (1.f + expf(-ig));
    float f_s = 1.f / (1.f + expf(-fg));
    float g_t = tanhf(gg);
    float o_s = 1.f / (1.f + expf(-og));
    float cc = f_s * g_c[idx] + i_s * g_t;
    g_c[idx] = cc;
    float h = o_s * tanhf(cc);
    __half a, bb;
    split2(h, a, bb);
    g_a0[b*KG + 512 + j] = a; g_a1[b*KG + 512 + j] = bb;
}

// ---------------- argmax finalize + embedding gather -------------------------
__global__ void finalize_kernel(const float* __restrict__ emb)
{
    int row = blockIdx.x;
    int t = threadIdx.x;          // 512 threads
    __shared__ float sv[512];
    __shared__ int   si[512];
    __shared__ int   nstar;
    float v = -INFINITY; int id = 0x7fffffff;
    if (t < NT2) { v = g_pval[t*BATCH + row]; id = g_pidx[t*BATCH + row]; }
    sv[t] = v; si[t] = id;
    __syncthreads();
    for (int s = 256; s > 0; s >>= 1) {
        if (t < s) {
            float ov = sv[t+s]; int oi = si[t+s];
            if (ov > sv[t] || (ov == sv[t] && oi < si[t])) { sv[t] = ov; si[t] = oi; }
        }
        __syncthreads();
    }
    if (t == 0) nstar = si[0];
    __syncthreads();
    if (t < 256) {
        int j = t * 2;
        float2 e = *(const float2*)&emb[(size_t)nstar*EMBED + j];
        __half a, b;
        split2(e.x, a, b);
        g_a0[row*KG + j] = a; g_a1[row*KG + j] = b;
        split2(e.y, a, b);
        g_a0[row*KG + j + 1] = a; g_a1[row*KG + j + 1] = b;
    }
}

// ---------------- launch ------------------------------------------------------
extern "C" void kernel_launch(void* const* d_in, const int* in_sizes, int n_in,
                              void* d_out, int out_size)
{
    const float* eh    = (const float*)d_in[0];
    const float* ec    = (const float*)d_in[1];
    const float* emb   = (const float*)d_in[2];
    const float* w_ih  = (const float*)d_in[3];
    const float* w_hh  = (const float*)d_in[4];
    const float* b_ih  = (const float*)d_in[5];
    const float* b_hh  = (const float*)d_in[6];
    const float* w_out = (const float*)d_in[7];
    const float* b_out = (const float*)d_in[8];
    const int*   sos   = (const int*)d_in[9];
    float* out = (float*)d_out;

    cudaFuncSetAttribute(gates_gemm,
                         cudaFuncAttributeMaxDynamicSharedMemorySize, G_SMEM);
    cudaFuncSetAttribute(logits_gemm,
                         cudaFuncAttributeMaxDynamicSharedMemorySize, L_SMEM);

    conv_wout_kernel<<<(int)(((size_t)VOCAB*KL/4 + 255)/256), 256>>>(w_out);
    conv_wg_kernel<<<(int)(((size_t)GATES4*KG/4 + 255)/256), 256>>>(w_ih, w_hh);
    init_kernel<<<(BATCH*VOCAB + 255)/256, 256>>>(eh, ec, emb, sos, out);

    for (int step = 1; step < MAXLEN; step++) {
        gates_gemm<<<dim3(GATES4/64, KSPLIT), 256, G_SMEM>>>();
        lstm_kernel<<<(BATCH*HIDDEN)/256, 256>>>(b_ih, b_hh);
        logits_gemm<<<NT2, 256, L_SMEM>>>(b_out, out + (size_t)step*BATCH*VOCAB);
        finalize_kernel<<<BATCH, 512>>>(emb);
    }
}

// round 13
// speedup vs baseline: 1.7021x; 1.7021x over previous
#include <cuda_runtime.h>
#include <cuda_fp16.h>
#include <math.h>
#include <stdint.h>

#define BATCH   128
#define HIDDEN  1024
#define EMBED   512
#define VOCAB   32000
#define MAXLEN  48
#define GATES4  4096
#define KL      1024          // logits K
#define KG      1536          // gates K
#define NT2     500           // logits N tiles of 64
#define GT      64            // gates N tiles of 64
#define STAGE_BYTES 49152     // A0,A1 (16KB) + B0,B1 (8KB)
#define SMEM_BYTES  (2*STAGE_BYTES)

// ---------------- persistent device state (no allocation) --------------------
__device__ __align__(16) __half g_a0[BATCH*KG];   // A: cols [0,512)=x, [512,1536)=h
__device__ __align__(16) __half g_a1[BATCH*KG];
__device__ __align__(16) __half g_w0[(size_t)VOCAB*KL];
__device__ __align__(16) __half g_w1[(size_t)VOCAB*KL];
__device__ __align__(16) __half g_g0[(size_t)GATES4*KG];
__device__ __align__(16) __half g_g1[(size_t)GATES4*KG];
__device__ float g_c[BATCH*HIDDEN];
__device__ float g_part[2*BATCH*GATES4];   // [0]=x-part, [1]=h-part
__device__ float g_pval[NT2*BATCH];
__device__ int   g_pidx[NT2*BATCH];

// ---------------- ptx helpers (base-family PTX, sm_80+) ----------------------
__device__ __forceinline__ uint32_t smem_u32(const void* p) {
    uint32_t a;
    asm("{ .reg .u64 t; cvta.to.shared.u64 t, %1; cvt.u32.u64 %0, t; }" : "=r"(a) : "l"(p));
    return a;
}
__device__ __forceinline__ void cpa16(uint32_t dst, const void* src) {
    asm volatile("cp.async.cg.shared.global [%0], [%1], 16;" :: "r"(dst), "l"(src));
}
__device__ __forceinline__ void cpa_commit() {
    asm volatile("cp.async.commit_group;" ::: "memory");
}
template<int N> __device__ __forceinline__ void cpa_wait() {
    asm volatile("cp.async.wait_group %0;" :: "n"(N) : "memory");
}
__device__ __forceinline__ void ldsm4(uint32_t* r, uint32_t addr) {
    asm volatile("ldmatrix.sync.aligned.m8n8.x4.shared.b16 {%0,%1,%2,%3}, [%4];"
                 : "=r"(r[0]), "=r"(r[1]), "=r"(r[2]), "=r"(r[3]) : "r"(addr));
}
__device__ __forceinline__ void mma16816(float* c, const uint32_t* a, uint32_t b0, uint32_t b1) {
    asm volatile(
        "mma.sync.aligned.m16n8k16.row.col.f32.f16.f16.f32 "
        "{%0,%1,%2,%3}, {%4,%5,%6,%7}, {%8,%9}, {%0,%1,%2,%3};"
        : "+f"(c[0]), "+f"(c[1]), "+f"(c[2]), "+f"(c[3])
        : "r"(a[0]), "r"(a[1]), "r"(a[2]), "r"(a[3]), "r"(b0), "r"(b1));
}
__device__ __forceinline__ uint32_t swz(uint32_t off) { return off ^ ((off >> 3) & 0x70); }

__device__ __forceinline__ void split2(float x, __half& a, __half& b) {
    a = __float2half_rn(x);
    b = __float2half_rn(x - __half2float(a));
}

// ---------------- weight conversion ------------------------------------------
__global__ void conv_wout_kernel(const float* __restrict__ w) {
    size_t i4 = ((size_t)blockIdx.x * 256 + threadIdx.x) * 4;
    if (i4 >= (size_t)VOCAB * KL) return;
    float4 v = *(const float4*)&w[i4];
    __half a[4], b[4];
    split2(v.x, a[0], b[0]); split2(v.y, a[1], b[1]);
    split2(v.z, a[2], b[2]); split2(v.w, a[3], b[3]);
#pragma unroll
    for (int j = 0; j < 4; j++) { g_w0[i4+j] = a[j]; g_w1[i4+j] = b[j]; }
}
__global__ void conv_wg_kernel(const float* __restrict__ w_ih, const float* __restrict__ w_hh) {
    size_t i4 = ((size_t)blockIdx.x * 256 + threadIdx.x) * 4;
    if (i4 >= (size_t)GATES4 * KG) return;
    int n = (int)(i4 / KG), k = (int)(i4 % KG);
    float4 v;
    if (k < EMBED) v = *(const float4*)&w_ih[(size_t)n*EMBED + k];
    else           v = *(const float4*)&w_hh[(size_t)n*HIDDEN + (k - EMBED)];
    __half a[4], b[4];
    split2(v.x, a[0], b[0]); split2(v.y, a[1], b[1]);
    split2(v.z, a[2], b[2]); split2(v.w, a[3], b[3]);
#pragma unroll
    for (int j = 0; j < 4; j++) { g_g0[i4+j] = a[j]; g_g1[i4+j] = b[j]; }
}

// ---------------- init -------------------------------------------------------
__global__ void init_kernel(const float* __restrict__ eh, const float* __restrict__ ec,
                            const float* __restrict__ emb, const int* __restrict__ sos,
                            float* __restrict__ out0)
{
    int idx = blockIdx.x * 256 + threadIdx.x;
    if (idx < BATCH*HIDDEN) {
        int bb = idx >> 10, j = idx & 1023;
        __half a, b;
        split2(eh[idx], a, b);
        g_a0[bb*KG + 512 + j] = a; g_a1[bb*KG + 512 + j] = b;
        g_c[idx] = ec[idx];
    }
    if (idx < BATCH*EMBED) {
        int bb = idx >> 9, j = idx & 511;
        __half a, b;
        split2(emb[(size_t)sos[0]*EMBED + j], a, b);
        g_a0[bb*KG + j] = a; g_a1[bb*KG + j] = b;
    }
    if (idx < BATCH*VOCAB) out0[idx] = 0.0f;
}

// ---------------- gates_x GEMM: x-part, K=512 --------------------------------
// C[128 x 64-tile] = A0*B0 + A0*B1 + A1*B0 over K [0,512). R7 mainloop.
__global__ __launch_bounds__(256, 2) void gates_x_gemm()
{
    extern __shared__ char smem[];
    const uint32_t sbase = smem_u32(smem);
    const int tid  = threadIdx.x;
    const int lane = tid & 31;
    const int warp = tid >> 5;
    const int wm = warp >> 1, wn = warp & 1;
    const int m_base = wm * 32, n_base = wn * 32;
    const int n0     = blockIdx.x * 64;
    const int NC = 512 / 64;  // 8

    auto load_stage = [&](int buf, int c) {
        uint32_t sdst = sbase + buf * STAGE_BYTES;
        const int kc = c * 64;
#pragma unroll
        for (int i = 0; i < 12; i++) {
            const int idx = i * 256 + tid;
            if (idx < 2048) {
                const int t = idx >> 10, rem = idx & 1023;
                const int row = rem >> 3, ch = rem & 7;
                cpa16(sdst + t * 16384 + swz((uint32_t)(row * 128 + ch * 16)),
                      (t ? g_a1 : g_a0) + row * KG + kc + ch * 8);
            } else {
                const int t = (idx - 2048) >> 9, rem = idx & 511;
                const int row = rem >> 3, ch = rem & 7;
                cpa16(sdst + 32768 + t * 8192 + swz((uint32_t)(row * 128 + ch * 16)),
                      (t ? g_g1 : g_g0) + (size_t)(n0 + row) * KG + kc + ch * 8);
            }
        }
    };

    float acc[2][4][4];
#pragma unroll
    for (int i = 0; i < 2; i++)
#pragma unroll
        for (int j = 0; j < 4; j++)
#pragma unroll
            for (int q = 0; q < 4; q++) acc[i][j][q] = 0.f;

    load_stage(0, 0); cpa_commit();

#pragma unroll 1
    for (int c = 0; c < NC; c++) {
        if (c + 1 < NC) { load_stage((c + 1) & 1, c + 1); cpa_commit(); cpa_wait<1>(); }
        else            { cpa_wait<0>(); }
        __syncthreads();

        const uint32_t sb  = sbase + (c & 1) * STAGE_BYTES;
        const uint32_t sA0 = sb, sA1 = sb + 16384, sB0 = sb + 32768, sB1 = sb + 40960;
#pragma unroll
        for (int ks = 0; ks < 4; ks++) {
            const uint32_t kb = (uint32_t)(ks * 32 + ((lane >> 4) << 4));
            uint32_t a0[2][4], a1[2][4], b0[2][4], b1[2][4];
#pragma unroll
            for (int mt = 0; mt < 2; mt++) {
                const uint32_t roff = swz((uint32_t)((m_base + mt*16 + (lane & 15)) * 128) + kb);
                ldsm4(a0[mt], sA0 + roff);
                ldsm4(a1[mt], sA1 + roff);
            }
#pragma unroll
            for (int nh = 0; nh < 2; nh++) {
                const uint32_t roff = swz((uint32_t)((n_base + nh*16 + (lane & 15)) * 128) + kb);
                ldsm4(b0[nh], sB0 + roff);
                ldsm4(b1[nh], sB1 + roff);
            }
#pragma unroll
            for (int mt = 0; mt < 2; mt++)
#pragma unroll
                for (int nt = 0; nt < 4; nt++) {
                    const int nh = nt >> 1, hi = nt & 1;
                    mma16816(acc[mt][nt], a0[mt], b0[nh][hi], b0[nh][hi + 2]);
                }
#pragma unroll
            for (int mt = 0; mt < 2; mt++)
#pragma unroll
                for (int nt = 0; nt < 4; nt++) {
                    const int nh = nt >> 1, hi = nt & 1;
                    mma16816(acc[mt][nt], a0[mt], b1[nh][hi], b1[nh][hi + 2]);
                }
#pragma unroll
            for (int mt = 0; mt < 2; mt++)
#pragma unroll
                for (int nt = 0; nt < 4; nt++) {
                    const int nh = nt >> 1, hi = nt & 1;
                    mma16816(acc[mt][nt], a1[mt], b0[nh][hi], b0[nh][hi + 2]);
                }
        }
        __syncthreads();
    }

    float* o = g_part;   // x-part buffer
#pragma unroll
    for (int mt = 0; mt < 2; mt++) {
        const int r0 = m_base + mt * 16 + (lane >> 2);
#pragma unroll
        for (int nt = 0; nt < 4; nt++) {
            const int col = n0 + n_base + nt * 8 + (lane & 3) * 2;
            *(float2*)&o[(size_t)r0 * GATES4 + col]       = make_float2(acc[mt][nt][0], acc[mt][nt][1]);
            *(float2*)&o[(size_t)(r0 + 8) * GATES4 + col] = make_float2(acc[mt][nt][2], acc[mt][nt][3]);
        }
    }
}

// ---------------- combined kernel: logits tiles + gates_h tiles --------------
// bid < NT2: logits tile (K=1024 over w_out splits, +bias, argmax).
// bid >= NT2: gates_h tile (K=1024 over w_hh part of g_g*, -> g_part[1]).
// `base` is added to blockIdx.x so a 64-CTA pre-loop launch can run gates_h only.
__global__ __launch_bounds__(256, 2) void combined_gemm(
    const float* __restrict__ bias, float* __restrict__ out, int base)
{
    extern __shared__ char smem[];
    const uint32_t sbase = smem_u32(smem);
    const int tid  = threadIdx.x;
    const int lane = tid & 31;
    const int warp = tid >> 5;
    const int wm = warp >> 1, wn = warp & 1;
    const int m_base = wm * 32, n_base = wn * 32;
    const int bid    = blockIdx.x + base;
    const bool isL   = (bid < NT2);
    const int n0     = isL ? bid * 64 : (bid - NT2) * 64;
    const int NC = KL / 64;  // 16

    const __half* B0 = isL ? g_w0 : g_g0;
    const __half* B1 = isL ? g_w1 : g_g1;
    const int bstride = isL ? KL : KG;
    const int bcol0   = isL ? 0 : 512;

    auto load_stage = [&](int buf, int c) {
        uint32_t sdst = sbase + buf * STAGE_BYTES;
        const int kc = c * 64;
#pragma unroll
        for (int i = 0; i < 12; i++) {
            const int idx = i * 256 + tid;
            if (idx < 2048) {
                const int t = idx >> 10, rem = idx & 1023;
                const int row = rem >> 3, ch = rem & 7;
                cpa16(sdst + t * 16384 + swz((uint32_t)(row * 128 + ch * 16)),
                      (t ? g_a1 : g_a0) + row * KG + 512 + kc + ch * 8);
            } else {
                const int t = (idx - 2048) >> 9, rem = idx & 511;
                const int row = rem >> 3, ch = rem & 7;
                cpa16(sdst + 32768 + t * 8192 + swz((uint32_t)(row * 128 + ch * 16)),
                      (t ? B1 : B0) + (size_t)(n0 + row) * bstride + bcol0 + kc + ch * 8);
            }
        }
    };

    float acc[2][4][4];
#pragma unroll
    for (int i = 0; i < 2; i++)
#pragma unroll
        for (int j = 0; j < 4; j++)
#pragma unroll
            for (int q = 0; q < 4; q++) acc[i][j][q] = 0.f;

    load_stage(0, 0); cpa_commit();

#pragma unroll 1
    for (int c = 0; c < NC; c++) {
        if (c + 1 < NC) { load_stage((c + 1) & 1, c + 1); cpa_commit(); cpa_wait<1>(); }
        else            { cpa_wait<0>(); }
        __syncthreads();

        const uint32_t sb  = sbase + (c & 1) * STAGE_BYTES;
        const uint32_t sA0 = sb, sA1 = sb + 16384, sB0 = sb + 32768, sB1 = sb + 40960;
#pragma unroll
        for (int ks = 0; ks < 4; ks++) {
            const uint32_t kb = (uint32_t)(ks * 32 + ((lane >> 4) << 4));
            uint32_t a0[2][4], a1[2][4], b0[2][4], b1[2][4];
#pragma unroll
            for (int mt = 0; mt < 2; mt++) {
                const uint32_t roff = swz((uint32_t)((m_base + mt*16 + (lane & 15)) * 128) + kb);
                ldsm4(a0[mt], sA0 + roff);
                ldsm4(a1[mt], sA1 + roff);
            }
#pragma unroll
            for (int nh = 0; nh < 2; nh++) {
                const uint32_t roff = swz((uint32_t)((n_base + nh*16 + (lane & 15)) * 128) + kb);
                ldsm4(b0[nh], sB0 + roff);
                ldsm4(b1[nh], sB1 + roff);
            }
#pragma unroll
            for (int mt = 0; mt < 2; mt++)
#pragma unroll
                for (int nt = 0; nt < 4; nt++) {
                    const int nh = nt >> 1, hi = nt & 1;
                    mma16816(acc[mt][nt], a0[mt], b0[nh][hi], b0[nh][hi + 2]);
                }
#pragma unroll
            for (int mt = 0; mt < 2; mt++)
#pragma unroll
                for (int nt = 0; nt < 4; nt++) {
                    const int nh = nt >> 1, hi = nt & 1;
                    mma16816(acc[mt][nt], a0[mt], b1[nh][hi], b1[nh][hi + 2]);
                }
#pragma unroll
            for (int mt = 0; mt < 2; mt++)
#pragma unroll
                for (int nt = 0; nt < 4; nt++) {
                    const int nh = nt >> 1, hi = nt & 1;
                    mma16816(acc[mt][nt], a1[mt], b0[nh][hi], b0[nh][hi + 2]);
                }
        }
        __syncthreads();
    }

    // -------------------------- epilogue ------------------------------------
    if (!isL) {
        float* o = g_part + (size_t)BATCH * GATES4;   // h-part buffer
#pragma unroll
        for (int mt = 0; mt < 2; mt++) {
            const int r0 = m_base + mt * 16 + (lane >> 2);
#pragma unroll
            for (int nt = 0; nt < 4; nt++) {
                const int col = n0 + n_base + nt * 8 + (lane & 3) * 2;
                *(float2*)&o[(size_t)r0 * GATES4 + col]       = make_float2(acc[mt][nt][0], acc[mt][nt][1]);
                *(float2*)&o[(size_t)(r0 + 8) * GATES4 + col] = make_float2(acc[mt][nt][2], acc[mt][nt][3]);
            }
        }
    } else {
        float2 bv[4];
#pragma unroll
        for (int nt = 0; nt < 4; nt++)
            bv[nt] = *(const float2*)&bias[n0 + n_base + nt * 8 + (lane & 3) * 2];

        float* rv = (float*)smem;               // reuse stage smem (post-sync)
        int*   ri = (int*)(smem + 2048);

#pragma unroll
        for (int mt = 0; mt < 2; mt++) {
#pragma unroll
            for (int half = 0; half < 2; half++) {
                const int row = m_base + mt * 16 + (lane >> 2) + half * 8;
                float best = -INFINITY; int bidx = 0;
#pragma unroll
                for (int nt = 0; nt < 4; nt++) {
                    const int col = n0 + n_base + nt * 8 + (lane & 3) * 2;
                    float v0 = acc[mt][nt][half*2]   + bv[nt].x;
                    float v1 = acc[mt][nt][half*2+1] + bv[nt].y;
                    *(float2*)&out[(size_t)row * VOCAB + col] = make_float2(v0, v1);
                    if (v0 > best) { best = v0; bidx = col; }
                    if (v1 > best) { best = v1; bidx = col + 1; }
                }
#pragma unroll
                for (int off = 1; off <= 2; off <<= 1) {
                    float ov = __shfl_xor_sync(0xffffffffu, best, off);
                    int   oi = __shfl_xor_sync(0xffffffffu, bidx, off);
                    if (ov > best || (ov == best && oi < bidx)) { best = ov; bidx = oi; }
                }
                if ((lane & 3) == 0) { rv[row * 2 + wn] = best; ri[row * 2 + wn] = bidx; }
            }
        }
        __syncthreads();
        if (tid < 128) {
            float best = rv[tid * 2]; int bidx = ri[tid * 2];
            float ov = rv[tid * 2 + 1]; int oi = ri[tid * 2 + 1];
            if (ov > best || (ov == best && oi < bidx)) { best = ov; bidx = oi; }
            g_pval[bid * BATCH + tid] = best;
            g_pidx[bid * BATCH + tid] = bidx;
        }
    }
}

// ---------------- LSTM elementwise (sums x-part + h-part) --------------------
__global__ void lstm_kernel(const float* __restrict__ b_ih, const float* __restrict__ b_hh)
{
    int idx = blockIdx.x * 256 + threadIdx.x;     // < 128*1024
    int b = idx >> 10, j = idx & 1023;
    const int o = b * GATES4 + j;
    const float* Px = g_part;
    const float* Ph = g_part + (size_t)BATCH * GATES4;
    float ig = Px[o]        + Ph[o]        + b_ih[j]        + b_hh[j];
    float fg = Px[o + 1024] + Ph[o + 1024] + b_ih[1024 + j] + b_hh[1024 + j];
    float gg = Px[o + 2048] + Ph[o + 2048] + b_ih[2048 + j] + b_hh[2048 + j];
    float og = Px[o + 3072] + Ph[o + 3072] + b_ih[3072 + j] + b_hh[3072 + j];
    float i_s = 1.f / (1.f + expf(-ig));
    float f_s = 1.f / (1.f + expf(-fg));
    float g_t = tanhf(gg);
    float o_s = 1.f / (1.f + expf(-og));
    float cc = f_s * g_c[idx] + i_s * g_t;
    g_c[idx] = cc;
    float h = o_s * tanhf(cc);
    __half a, bb;
    split2(h, a, bb);
    g_a0[b*KG + 512 + j] = a; g_a1[b*KG + 512 + j] = bb;
}

// ---------------- argmax finalize + embedding gather -------------------------
__global__ void finalize_kernel(const float* __restrict__ emb)
{
    int row = blockIdx.x;
    int t = threadIdx.x;          // 512 threads
    __shared__ float sv[512];
    __shared__ int   si[512];
    __shared__ int   nstar;
    float v = -INFINITY; int id = 0x7fffffff;
    if (t < NT2) { v = g_pval[t*BATCH + row]; id = g_pidx[t*BATCH + row]; }
    sv[t] = v; si[t] = id;
    __syncthreads();
    for (int s = 256; s > 0; s >>= 1) {
        if (t < s) {
            float ov = sv[t+s]; int oi = si[t+s];
            if (ov > sv[t] || (ov == sv[t] && oi < si[t])) { sv[t] = ov; si[t] = oi; }
        }
        __syncthreads();
    }
    if (t == 0) nstar = si[0];
    __syncthreads();
    if (t < 256) {
        int j = t * 2;
        float2 e = *(const float2*)&emb[(size_t)nstar*EMBED + j];
        __half a, b;
        split2(e.x, a, b);
        g_a0[row*KG + j] = a; g_a1[row*KG + j] = b;
        split2(e.y, a, b);
        g_a0[row*KG + j + 1] = a; g_a1[row*KG + j + 1] = b;
    }
}

// ---------------- launch ------------------------------------------------------
extern "C" void kernel_launch(void* const* d_in, const int* in_sizes, int n_in,
                              void* d_out, int out_size)
{
    const float* eh    = (const float*)d_in[0];
    const float* ec    = (const float*)d_in[1];
    const float* emb   = (const float*)d_in[2];
    const float* w_ih  = (const float*)d_in[3];
    const float* w_hh  = (const float*)d_in[4];
    const float* b_ih  = (const float*)d_in[5];
    const float* b_hh  = (const float*)d_in[6];
    const float* w_out = (const float*)d_in[7];
    const float* b_out = (const float*)d_in[8];
    const int*   sos   = (const int*)d_in[9];
    float* out = (float*)d_out;

    cudaFuncSetAttribute(gates_x_gemm,
                         cudaFuncAttributeMaxDynamicSharedMemorySize, SMEM_BYTES);
    cudaFuncSetAttribute(combined_gemm,
                         cudaFuncAttributeMaxDynamicSharedMemorySize, SMEM_BYTES);

    conv_wout_kernel<<<(int)(((size_t)VOCAB*KL/4 + 255)/256), 256>>>(w_out);
    conv_wg_kernel<<<(int)(((size_t)GATES4*KG/4 + 255)/256), 256>>>(w_ih, w_hh);
    init_kernel<<<(BATCH*VOCAB + 255)/256, 256>>>(eh, ec, emb, sos, out);

    // pre-loop: h-part of gates for step 1 (h from init)
    combined_gemm<<<GT, 256, SMEM_BYTES>>>(b_out, out, NT2);

    for (int step = 1; step < MAXLEN; step++) {
        gates_x_gemm<<<GT, 256, SMEM_BYTES>>>();
        lstm_kernel<<<(BATCH*HIDDEN)/256, 256>>>(b_ih, b_hh);
        // logits for this step + h-part gates for next step
        combined_gemm<<<NT2 + GT, 256, SMEM_BYTES>>>(
            b_out, out + (size_t)step*BATCH*VOCAB, 0);
        finalize_kernel<<<BATCH, 512>>>(emb);
    }
}